// round 3
// baseline (speedup 1.0000x reference)
#include <cuda_runtime.h>

#define TT 1024
#define BB 32
#define II 512
#define HH 512
#define GG 2048   // 4*H

struct __align__(16) u64x2 { unsigned long long a, b; };

__device__ __forceinline__ unsigned long long ffma2(
    unsigned long long x, unsigned long long y, unsigned long long z)
{
    unsigned long long r;
    asm("fma.rn.f32x2 %0, %1, %2, %3;" : "=l"(r) : "l"(x), "l"(y), "l"(z));
    return r;
}
__device__ __forceinline__ void unpack2(float& lo, float& hi, unsigned long long v)
{
    asm("mov.b64 {%0, %1}, %2;" : "=f"(lo), "=f"(hi) : "l"(v));
}

// Scratch: gates_x in [t][g][b] layout (scan-friendly: lane=b coalesced)
__device__ float g_gates[(size_t)TT * GG * BB];
__device__ unsigned int g_bar_count;
__device__ unsigned int g_bar_gen;

// ---------------------------------------------------------------------------
// Kernel 1: gates_x = input @ W_ih^T + b_ih + b_hh, f32x2 packed FMA.
// A-duplicated smem (each a stored twice) so a-splat pairs load directly.
// ---------------------------------------------------------------------------
#define BM 128
#define BN 128
#define BK 16
#define LDP 132   // Bs pitch
#define A2P 268   // As2 pitch (2*128 + 12), %4==0, tuned for store banks

__global__ __launch_bounds__(256) void gemm_input(
    const float* __restrict__ A, const float* __restrict__ W,
    const float* __restrict__ b_ih, const float* __restrict__ b_hh)
{
    __shared__ __align__(16) float As2[BK * A2P];
    __shared__ __align__(16) float Bs[BK * LDP];
    const int tid = threadIdx.x;
    const int m0 = blockIdx.y * BM;
    const int n0 = blockIdx.x * BN;
    const int tm = (tid >> 4) * 8;
    const int tn = (tid & 15) * 8;

    unsigned long long acc2[8][4];
#pragma unroll
    for (int i = 0; i < 8; i++)
#pragma unroll
        for (int j = 0; j < 4; j++) acc2[i][j] = 0ull;

    for (int k0 = 0; k0 < II; k0 += BK) {
#pragma unroll
        for (int i = 0; i < 2; i++) {
            int f   = tid + i * 256;      // 0..511
            int row = f >> 2;             // 0..127
            int kq  = (f & 3) * 4;        // 0,4,8,12
            float4 va = *(const float4*)(A + (size_t)(m0 + row) * II + k0 + kq);
            // duplicate-store a so that u64 reads are splat pairs (a_m, a_m)
            *(float2*)&As2[(kq + 0) * A2P + 2 * row] = make_float2(va.x, va.x);
            *(float2*)&As2[(kq + 1) * A2P + 2 * row] = make_float2(va.y, va.y);
            *(float2*)&As2[(kq + 2) * A2P + 2 * row] = make_float2(va.z, va.z);
            *(float2*)&As2[(kq + 3) * A2P + 2 * row] = make_float2(va.w, va.w);
            float4 vb = *(const float4*)(W + (size_t)(n0 + row) * II + k0 + kq);
            Bs[(kq + 0) * LDP + row] = vb.x;
            Bs[(kq + 1) * LDP + row] = vb.y;
            Bs[(kq + 2) * LDP + row] = vb.z;
            Bs[(kq + 3) * LDP + row] = vb.w;
        }
        __syncthreads();
#pragma unroll
        for (int k = 0; k < BK; k++) {
            u64x2 av[4], bv[2];
#pragma unroll
            for (int q = 0; q < 4; q++)
                av[q] = *(const u64x2*)&As2[k * A2P + 2 * tm + 4 * q];
            bv[0] = *(const u64x2*)&Bs[k * LDP + tn];
            bv[1] = *(const u64x2*)&Bs[k * LDP + tn + 4];
#pragma unroll
            for (int q = 0; q < 4; q++) {
                int i0 = 2 * q;
                acc2[i0][0]     = ffma2(av[q].a, bv[0].a, acc2[i0][0]);
                acc2[i0][1]     = ffma2(av[q].a, bv[0].b, acc2[i0][1]);
                acc2[i0][2]     = ffma2(av[q].a, bv[1].a, acc2[i0][2]);
                acc2[i0][3]     = ffma2(av[q].a, bv[1].b, acc2[i0][3]);
                acc2[i0 + 1][0] = ffma2(av[q].b, bv[0].a, acc2[i0 + 1][0]);
                acc2[i0 + 1][1] = ffma2(av[q].b, bv[0].b, acc2[i0 + 1][1]);
                acc2[i0 + 1][2] = ffma2(av[q].b, bv[1].a, acc2[i0 + 1][2]);
                acc2[i0 + 1][3] = ffma2(av[q].b, bv[1].b, acc2[i0 + 1][3]);
            }
        }
        __syncthreads();
    }

    float bj[8];
#pragma unroll
    for (int j = 0; j < 8; j++) {
        int g = n0 + tn + j;
        bj[j] = b_ih[g] + b_hh[g];
    }
#pragma unroll
    for (int i = 0; i < 8; i++) {
        int m = m0 + tm + i;
        int t = m >> 5, b = m & 31;
        size_t base = ((size_t)t * GG) * BB + (size_t)b;
#pragma unroll
        for (int jp = 0; jp < 4; jp++) {
            float lo, hi;
            unpack2(lo, hi, acc2[i][jp]);
            int g = n0 + tn + 2 * jp;
            g_gates[base + (size_t)g * BB]       = lo + bj[2 * jp];
            g_gates[base + (size_t)(g + 1) * BB] = hi + bj[2 * jp + 1];
        }
    }
}

// ---------------------------------------------------------------------------
// Kernel 2: persistent LSTM scan, all 8 warps compute, f32x2 FMA.
// Block owns 4 h-cols (j0=4*blk). Warp wid: u2=wid&1 (col pair), kseg=wid>>1
// (k in [128*kseg, 128*kseg+128)). Lane l: c=l&1 (col j0+2*u2+c), b=l>>1
// (batches b and b+16). Thread: 4 gates x 2 batches partial dots over 128 k.
// Partials reduced across ksegs via smem; epilogue on tid<128.
// ---------------------------------------------------------------------------
#define NBLK 128
#define NTHR 256
#define HP 516    // h_sh pitch
#define WP 516    // W_sh pitch (padded so c-lanes hit distinct banks)
#define PCELL 20  // partial cell stride: 16 floats (g*4+kseg) + 4 pad

__device__ __forceinline__ void grid_barrier()
{
    __syncthreads();
    if (threadIdx.x == 0) {
        unsigned gen = *((volatile unsigned*)&g_bar_gen);
        __threadfence();
        if (atomicAdd(&g_bar_count, 1u) == NBLK - 1) {
            g_bar_count = 0;
            __threadfence();
            atomicAdd(&g_bar_gen, 1u);   // release
        } else {
            while (*((volatile unsigned*)&g_bar_gen) == gen) { }
        }
        __threadfence();
    }
    __syncthreads();
}

__global__ __launch_bounds__(NTHR) void lstm_scan(
    const float* __restrict__ h0, const float* __restrict__ c0,
    const float* __restrict__ W_hh, float* __restrict__ out, int out_size)
{
    extern __shared__ __align__(16) float smem[];
    float* W_sh  = smem;                     // 16 * WP floats
    float* h_sh  = smem + 16 * WP;           // 32 * HP floats
    float* part  = smem + 16 * WP + 32 * HP; // 128 * PCELL floats

    const int tid  = threadIdx.x;
    const int j0   = blockIdx.x * 4;
    const int wid  = tid >> 5;
    const int lane = tid & 31;

    // Preload this block's W_hh slice once (time-invariant).
    // c16 = g*4 + cidx  <->  gate-col = g*512 + j0 + cidx
    for (int f4 = tid; f4 < 16 * 128; f4 += NTHR) {
        int c = f4 >> 7, k4 = f4 & 127;
        int gcol = (c >> 2) * HH + j0 + (c & 3);
        *(float4*)&W_sh[c * WP + k4 * 4] =
            *(const float4*)&W_hh[(size_t)gcol * HH + k4 * 4];
    }

    // compute-role mapping
    const int u2   = wid & 1;
    const int kseg = wid >> 1;
    const int cw   = lane & 1;
    const int bw   = lane >> 1;            // 0..15
    const int cidx = 2 * u2 + cw;          // 0..3
    const int k0   = kseg * 128;

    // epilogue-role mapping (tid < 128): col j0+ue, batch be
    const int ue = tid >> 5;   // 0..3 when tid<128
    const int be = lane;

    float creg = 0.f, hreg = 0.f;
    if (tid < 128) creg = c0[be * HH + j0 + ue];

    float* outputs = out;   // [T][B][H]

    const float* hr0 = h_sh + bw * HP + k0;
    const float* hr1 = h_sh + (bw + 16) * HP + k0;
    const float* wr0 = W_sh + (0 * 4 + cidx) * WP + k0;
    const float* wr1 = W_sh + (1 * 4 + cidx) * WP + k0;
    const float* wr2 = W_sh + (2 * 4 + cidx) * WP + k0;
    const float* wr3 = W_sh + (3 * 4 + cidx) * WP + k0;

    for (int t = 0; t < TT; t++) {
        const float* hp = (t == 0) ? h0 : (outputs + (size_t)(t - 1) * BB * HH);
        // Cooperative load of full h_prev into shared.
#pragma unroll
        for (int r = 0; r < 16; r++) {
            int f4 = r * NTHR + tid;     // 0..4095
            int b2 = f4 >> 7, k4 = f4 & 127;
            *(float4*)&h_sh[b2 * HP + k4 * 4] =
                *(const float4*)&hp[b2 * HH + k4 * 4];
        }

        // Prefetch gates_x for the epilogue (independent of h).
        float gxi = 0.f, gxf = 0.f, gxg = 0.f, gxo = 0.f;
        if (tid < 128) {
            const float* gx = g_gates + (size_t)t * GG * BB;
            gxi = gx[(size_t)(0 * HH + j0 + ue) * BB + be];
            gxf = gx[(size_t)(1 * HH + j0 + ue) * BB + be];
            gxg = gx[(size_t)(2 * HH + j0 + ue) * BB + be];
            gxo = gx[(size_t)(3 * HH + j0 + ue) * BB + be];
        }
        __syncthreads();   // h_sh ready (also covers W_sh on t==0)

        // Partial dots: 4 gates x 2 batches over this warp's 128-k segment.
        unsigned long long aA0 = 0, aA1 = 0, aA2 = 0, aA3 = 0;  // batch bw
        unsigned long long aB0 = 0, aB1 = 0, aB2 = 0, aB3 = 0;  // batch bw+16
#pragma unroll 8
        for (int it = 0; it < 32; it++) {
            u64x2 hA = *(const u64x2*)(hr0 + it * 4);
            u64x2 hB = *(const u64x2*)(hr1 + it * 4);
            u64x2 w;
            w = *(const u64x2*)(wr0 + it * 4);
            aA0 = ffma2(hA.a, w.a, aA0); aA0 = ffma2(hA.b, w.b, aA0);
            aB0 = ffma2(hB.a, w.a, aB0); aB0 = ffma2(hB.b, w.b, aB0);
            w = *(const u64x2*)(wr1 + it * 4);
            aA1 = ffma2(hA.a, w.a, aA1); aA1 = ffma2(hA.b, w.b, aA1);
            aB1 = ffma2(hB.a, w.a, aB1); aB1 = ffma2(hB.b, w.b, aB1);
            w = *(const u64x2*)(wr2 + it * 4);
            aA2 = ffma2(hA.a, w.a, aA2); aA2 = ffma2(hA.b, w.b, aA2);
            aB2 = ffma2(hB.a, w.a, aB2); aB2 = ffma2(hB.b, w.b, aB2);
            w = *(const u64x2*)(wr3 + it * 4);
            aA3 = ffma2(hA.a, w.a, aA3); aA3 = ffma2(hA.b, w.b, aA3);
            aB3 = ffma2(hB.a, w.a, aB3); aB3 = ffma2(hB.b, w.b, aB3);
        }
        // Reduce pairs and write partials: part[(cidx*32+bb)*PCELL + g*4 + kseg]
        {
            float lo, hi;
            int baseA = (cidx * 32 + bw) * PCELL + kseg;
            int baseB = (cidx * 32 + bw + 16) * PCELL + kseg;
            unpack2(lo, hi, aA0); part[baseA + 0]  = lo + hi;
            unpack2(lo, hi, aA1); part[baseA + 4]  = lo + hi;
            unpack2(lo, hi, aA2); part[baseA + 8]  = lo + hi;
            unpack2(lo, hi, aA3); part[baseA + 12] = lo + hi;
            unpack2(lo, hi, aB0); part[baseB + 0]  = lo + hi;
            unpack2(lo, hi, aB1); part[baseB + 4]  = lo + hi;
            unpack2(lo, hi, aB2); part[baseB + 8]  = lo + hi;
            unpack2(lo, hi, aB3); part[baseB + 12] = lo + hi;
        }
        __syncthreads();

        if (tid < 128) {
            const float* cell = &part[(ue * 32 + be) * PCELL];
            float4 p0 = *(const float4*)(cell + 0);
            float4 p1 = *(const float4*)(cell + 4);
            float4 p2 = *(const float4*)(cell + 8);
            float4 p3 = *(const float4*)(cell + 12);
            float ai = gxi + p0.x + p0.y + p0.z + p0.w;
            float af = gxf + p1.x + p1.y + p1.z + p1.w;
            float ag = gxg + p2.x + p2.y + p2.z + p2.w;
            float ao = gxo + p3.x + p3.y + p3.z + p3.w;

            float ig  = 1.f / (1.f + __expf(-ai));
            float fg  = 1.f / (1.f + __expf(-af));
            float gg2 = tanhf(ag);
            float og  = 1.f / (1.f + __expf(-ao));
            creg = fg * creg + ig * gg2;
            hreg = og * tanhf(creg);
            outputs[(size_t)t * BB * HH + (size_t)be * HH + j0 + ue] = hreg;
        }
        grid_barrier();   // h_t globally visible; protects h_sh/part reuse
    }

    // Tail: h_f then c_f appended after outputs.
    if (tid < 128) {
        size_t off = (size_t)TT * BB * HH;
        if ((size_t)out_size >= off + 2u * BB * HH) {
            out[off + (size_t)be * HH + j0 + ue]           = hreg;
            out[off + BB * HH + (size_t)be * HH + j0 + ue] = creg;
        }
    }
}

// ---------------------------------------------------------------------------
extern "C" void kernel_launch(void* const* d_in, const int* in_sizes, int n_in,
                              void* d_out, int out_size)
{
    const float* input = (const float*)d_in[0];
    const float* h0    = (const float*)d_in[1];
    const float* c0    = (const float*)d_in[2];
    const float* W_ih  = (const float*)d_in[3];
    const float* W_hh  = (const float*)d_in[4];
    const float* b_ih  = (const float*)d_in[5];
    const float* b_hh  = (const float*)d_in[6];

    size_t smem = (size_t)(16 * WP + 32 * HP + 128 * PCELL) * sizeof(float);
    cudaFuncSetAttribute(lstm_scan, cudaFuncAttributeMaxDynamicSharedMemorySize,
                         (int)smem);

    dim3 g1(GG / BN, (TT * BB) / BM);   // 16 x 256 blocks
    gemm_input<<<g1, 256>>>(input, W_ih, b_ih, b_hh);
    lstm_scan<<<NBLK, NTHR, smem>>>(h0, c0, W_hh, (float*)d_out, out_size);
}

// round 9
// speedup vs baseline: 1.5778x; 1.5778x over previous
#include <cuda_runtime.h>

#define TT 1024
#define BB 32
#define II 512
#define HH 512
#define GG 2048   // 4*H

struct __align__(16) u64x2 { unsigned long long a, b; };

__device__ __forceinline__ unsigned long long ffma2(
    unsigned long long x, unsigned long long y, unsigned long long z)
{
    unsigned long long r;
    asm("fma.rn.f32x2 %0, %1, %2, %3;" : "=l"(r) : "l"(x), "l"(y), "l"(z));
    return r;
}
__device__ __forceinline__ void unpack2(float& lo, float& hi, unsigned long long v)
{
    asm("mov.b64 {%0, %1}, %2;" : "=f"(lo), "=f"(hi) : "l"(v));
}

// Scratch: gates_x in [t][g][b] layout (scan-friendly: lane=b coalesced)
__device__ float g_gates[(size_t)TT * GG * BB];
__device__ unsigned int g_bar_count;
__device__ unsigned int g_bar_gen;

// ---------------------------------------------------------------------------
// Kernel 1: gates_x[t,b,g] = sum_i input[t,b,i] * W_ih[g,i] + b_ih[g] + b_hh[g]
// (R1 version, verbatim — measured ~1.37 ms)
// ---------------------------------------------------------------------------
#define BM 128
#define BN 128
#define BK 16
#define LDP 132

__global__ __launch_bounds__(256) void gemm_input(
    const float* __restrict__ A, const float* __restrict__ W,
    const float* __restrict__ b_ih, const float* __restrict__ b_hh)
{
    __shared__ __align__(16) float As[BK * LDP];
    __shared__ __align__(16) float Bs[BK * LDP];
    const int tid = threadIdx.x;
    const int m0 = blockIdx.y * BM;
    const int n0 = blockIdx.x * BN;
    const int tm = (tid >> 4) * 8;
    const int tn = (tid & 15) * 8;

    float acc[8][8];
#pragma unroll
    for (int i = 0; i < 8; i++)
#pragma unroll
        for (int j = 0; j < 8; j++) acc[i][j] = 0.f;

    for (int k0 = 0; k0 < II; k0 += BK) {
#pragma unroll
        for (int i = 0; i < 2; i++) {
            int f   = tid + i * 256;      // 0..511
            int row = f >> 2;             // 0..127
            int kq  = (f & 3) * 4;        // 0,4,8,12
            float4 va = *(const float4*)(A + (size_t)(m0 + row) * II + k0 + kq);
            As[(kq + 0) * LDP + row] = va.x;
            As[(kq + 1) * LDP + row] = va.y;
            As[(kq + 2) * LDP + row] = va.z;
            As[(kq + 3) * LDP + row] = va.w;
            float4 vb = *(const float4*)(W + (size_t)(n0 + row) * II + k0 + kq);
            Bs[(kq + 0) * LDP + row] = vb.x;
            Bs[(kq + 1) * LDP + row] = vb.y;
            Bs[(kq + 2) * LDP + row] = vb.z;
            Bs[(kq + 3) * LDP + row] = vb.w;
        }
        __syncthreads();
#pragma unroll
        for (int k = 0; k < BK; k++) {
            float a[8], bb[8];
            *(float4*)&a[0]  = *(float4*)&As[k * LDP + tm];
            *(float4*)&a[4]  = *(float4*)&As[k * LDP + tm + 4];
            *(float4*)&bb[0] = *(float4*)&Bs[k * LDP + tn];
            *(float4*)&bb[4] = *(float4*)&Bs[k * LDP + tn + 4];
#pragma unroll
            for (int i = 0; i < 8; i++)
#pragma unroll
                for (int j = 0; j < 8; j++) acc[i][j] += a[i] * bb[j];
        }
        __syncthreads();
    }

    float bj[8];
#pragma unroll
    for (int j = 0; j < 8; j++) {
        int g = n0 + tn + j;
        bj[j] = b_ih[g] + b_hh[g];
    }
#pragma unroll
    for (int i = 0; i < 8; i++) {
        int m = m0 + tm + i;
        int t = m >> 5, b = m & 31;
        size_t base = ((size_t)t * GG) * BB + (size_t)b;
#pragma unroll
        for (int j = 0; j < 8; j++) {
            int g = n0 + tn + j;
            g_gates[base + (size_t)g * BB] = acc[i][j] + bj[j];
        }
    }
}

// ---------------------------------------------------------------------------
// Kernel 2: persistent LSTM scan, 128 blocks x 256 threads.
// PROVEN R1 grid barrier (sense-reversing, single counter + generation) +
// R6 compute mapping (all 8 warps, f32x2; warp=kseg 64-k, lane: cidx=lane&3,
// bg=lane>>2; thread: 4 gates x 4 batches partial dots; smem reduction).
// ---------------------------------------------------------------------------
#define NBLK 128
#define NTHR 256
#define HP 516
#define WP 516
#define PCELL 36   // 4 gates x 8 ksegs = 32 floats + 4 pad

__device__ __forceinline__ void grid_barrier()
{
    __syncthreads();
    if (threadIdx.x == 0) {
        unsigned gen = *((volatile unsigned*)&g_bar_gen);
        __threadfence();
        if (atomicAdd(&g_bar_count, 1u) == NBLK - 1) {
            g_bar_count = 0;
            __threadfence();
            atomicAdd(&g_bar_gen, 1u);   // release
        } else {
            while (*((volatile unsigned*)&g_bar_gen) == gen) { }
        }
        __threadfence();
    }
    __syncthreads();
}

__global__ __launch_bounds__(NTHR) void lstm_scan(
    const float* __restrict__ h0, const float* __restrict__ c0,
    const float* __restrict__ W_hh, float* __restrict__ out, int out_size)
{
    extern __shared__ __align__(16) float smem[];
    float* W_sh = smem;                      // 16 * WP
    float* h_sh = smem + 16 * WP;            // 32 * HP
    float* part = smem + 16 * WP + 32 * HP;  // 128 * PCELL

    const int tid  = threadIdx.x;
    const int bid  = blockIdx.x;
    const int j0   = bid * 4;
    const int wid  = tid >> 5;
    const int lane = tid & 31;

    // Preload this block's W_hh slice once (time-invariant).
    for (int f4 = tid; f4 < 16 * 128; f4 += NTHR) {
        int c = f4 >> 7, k4 = f4 & 127;
        int gcol = (c >> 2) * HH + j0 + (c & 3);   // c = gate*4 + cidx
        *(float4*)&W_sh[c * WP + k4 * 4] =
            *(const float4*)&W_hh[(size_t)gcol * HH + k4 * 4];
    }

    // compute-role mapping
    const int kseg = wid;                  // 0..7
    const int k0   = kseg * 64;
    const int cidx = lane & 3;             // 0..3
    const int bg   = lane >> 2;            // 0..7; batches bg + 8*bb

    // epilogue-role mapping (tid < 128): col j0+ue, batch be
    const int ue = tid >> 5;
    const int be = lane;

    float creg = 0.f, hreg = 0.f;
    if (tid < 128) creg = c0[be * HH + j0 + ue];

    float* outputs = out;   // [T][B][H]

    const float* hr[4];
    const float* wr[4];
#pragma unroll
    for (int bb = 0; bb < 4; bb++) hr[bb] = h_sh + (bg + 8 * bb) * HP + k0;
#pragma unroll
    for (int g = 0; g < 4; g++)    wr[g]  = W_sh + (g * 4 + cidx) * WP + k0;

    for (int t = 0; t < TT; t++) {
        const float* hp = (t == 0) ? h0 : (outputs + (size_t)(t - 1) * BB * HH);

        // Prefetch gates_x (DRAM) early; lands before the epilogue.
        float gxi = 0.f, gxf = 0.f, gxg = 0.f, gxo = 0.f;
        if (tid < 128) {
            const float* gx = g_gates + (size_t)t * GG * BB;
            gxi = gx[(size_t)(0 * HH + j0 + ue) * BB + be];
            gxf = gx[(size_t)(1 * HH + j0 + ue) * BB + be];
            gxg = gx[(size_t)(2 * HH + j0 + ue) * BB + be];
            gxo = gx[(size_t)(3 * HH + j0 + ue) * BB + be];
        }

        // Cooperative load h_prev -> shared (h_{t-1} published by the
        // grid_barrier at the end of step t-1; h0 for t==0).
#pragma unroll
        for (int r = 0; r < 16; r++) {
            int f4 = r * NTHR + tid;
            int b2 = f4 >> 7, k4 = f4 & 127;
            *(float4*)&h_sh[b2 * HP + k4 * 4] =
                *(const float4*)&hp[b2 * HH + k4 * 4];
        }
        __syncthreads();   // h_sh ready (also covers W_sh preload on t==0)

        // Partial dots: 4 gates x 4 batches over this warp's 64-k segment.
        unsigned long long acc[4][4];
#pragma unroll
        for (int g = 0; g < 4; g++)
#pragma unroll
            for (int bb = 0; bb < 4; bb++) acc[g][bb] = 0ull;

#pragma unroll 4
        for (int it = 0; it < 16; it++) {
            u64x2 hv[4];
#pragma unroll
            for (int bb = 0; bb < 4; bb++)
                hv[bb] = *(const u64x2*)(hr[bb] + it * 4);
#pragma unroll
            for (int g = 0; g < 4; g++) {
                u64x2 w = *(const u64x2*)(wr[g] + it * 4);
#pragma unroll
                for (int bb = 0; bb < 4; bb++) {
                    acc[g][bb] = ffma2(hv[bb].a, w.a, acc[g][bb]);
                    acc[g][bb] = ffma2(hv[bb].b, w.b, acc[g][bb]);
                }
            }
        }
#pragma unroll
        for (int g = 0; g < 4; g++)
#pragma unroll
            for (int bb = 0; bb < 4; bb++) {
                float lo, hi;
                unpack2(lo, hi, acc[g][bb]);
                part[(cidx * 32 + bg + 8 * bb) * PCELL + g * 8 + kseg] = lo + hi;
            }
        __syncthreads();   // partials ready

        if (tid < 128) {
            const float* cell = &part[(ue * 32 + be) * PCELL];
            float ai = gxi, af = gxf, ag = gxg, ao = gxo;
#pragma unroll
            for (int q = 0; q < 2; q++) {
                float4 p0 = *(const float4*)(cell + 0  + q * 4);
                float4 p1 = *(const float4*)(cell + 8  + q * 4);
                float4 p2 = *(const float4*)(cell + 16 + q * 4);
                float4 p3 = *(const float4*)(cell + 24 + q * 4);
                ai += p0.x + p0.y + p0.z + p0.w;
                af += p1.x + p1.y + p1.z + p1.w;
                ag += p2.x + p2.y + p2.z + p2.w;
                ao += p3.x + p3.y + p3.z + p3.w;
            }
            float ig  = 1.f / (1.f + __expf(-ai));
            float fg  = 1.f / (1.f + __expf(-af));
            float gg2 = tanhf(ag);
            float og  = 1.f / (1.f + __expf(-ao));
            creg = fg * creg + ig * gg2;
            hreg = og * tanhf(creg);
            outputs[(size_t)t * BB * HH + (size_t)be * HH + j0 + ue] = hreg;
        }
        grid_barrier();   // publish h_t globally; protects h_sh/part reuse
    }

    // Tail: h_f then c_f appended after outputs.
    if (tid < 128) {
        size_t off = (size_t)TT * BB * HH;
        if ((size_t)out_size >= off + 2u * BB * HH) {
            out[off + (size_t)be * HH + j0 + ue]           = hreg;
            out[off + BB * HH + (size_t)be * HH + j0 + ue] = creg;
        }
    }
}

// ---------------------------------------------------------------------------
extern "C" void kernel_launch(void* const* d_in, const int* in_sizes, int n_in,
                              void* d_out, int out_size)
{
    const float* input = (const float*)d_in[0];
    const float* h0    = (const float*)d_in[1];
    const float* c0    = (const float*)d_in[2];
    const float* W_ih  = (const float*)d_in[3];
    const float* W_hh  = (const float*)d_in[4];
    const float* b_ih  = (const float*)d_in[5];
    const float* b_hh  = (const float*)d_in[6];

    size_t smem = (size_t)(16 * WP + 32 * HP + 128 * PCELL) * sizeof(float);
    cudaFuncSetAttribute(lstm_scan, cudaFuncAttributeMaxDynamicSharedMemorySize,
                         (int)smem);

    dim3 g1(GG / BN, (TT * BB) / BM);   // 16 x 256 blocks
    gemm_input<<<g1, 256>>>(input, W_ih, b_ih, b_hh);
    lstm_scan<<<NBLK, NTHR, smem>>>(h0, c0, W_hh, (float*)d_out, out_size);
}